// round 14
// baseline (speedup 1.0000x reference)
#include <cuda_runtime.h>
#include <cuda_fp16.h>
#include <math.h>

// Problem constants
#define NB 64
#define NS 512
#define NPIX (NS * NS)          // 262144
#define HF_COUNT 245760.0f      // 512*512 - 128*128

// -------- scratch (device globals; no allocation allowed) --------
__device__ __half2 g_Bf[NB * NPIX];  // 67 MB: pass-1 output (fp16 complex), TRANSPOSED
__device__ float2  g_tw[512];        // twiddles w^k = exp(-2*pi*i*k/512)
__device__ float   g_part[NB][256];  // per-(batch, v-pair) partial sums (deterministic)

// -------- complex helpers --------
static __device__ __forceinline__ float2 cadd(float2 a, float2 b) { return make_float2(a.x + b.x, a.y + b.y); }
static __device__ __forceinline__ float2 csub(float2 a, float2 b) { return make_float2(a.x - b.x, a.y - b.y); }
static __device__ __forceinline__ float2 cmul(float2 a, float2 w) {
    return make_float2(fmaf(a.x, w.x, -a.y * w.y), fmaf(a.x, w.y, a.y * w.x));
}

// DFT-8 (DIF internally, output in natural order X[0..7])
static __device__ __forceinline__ void dft8(const float2 a[8], float2 X[8]) {
    const float r = 0.70710678118654752440f;
    float2 s0 = cadd(a[0], a[4]), d0 = csub(a[0], a[4]);
    float2 s1 = cadd(a[1], a[5]), d1 = csub(a[1], a[5]);
    float2 s2 = cadd(a[2], a[6]), d2 = csub(a[2], a[6]);
    float2 s3 = cadd(a[3], a[7]), d3 = csub(a[3], a[7]);
    float2 d1t = make_float2(r * (d1.x + d1.y), r * (d1.y - d1.x));
    float2 d2t = make_float2(d2.y, -d2.x);
    float2 d3t = make_float2(r * (d3.y - d3.x), -r * (d3.x + d3.y));
    float2 u0 = cadd(s0, s2), u2 = csub(s0, s2);
    float2 u1 = cadd(s1, s3);
    float2 u3t = csub(s1, s3);
    float2 u3 = make_float2(u3t.y, -u3t.x);
    X[0] = cadd(u0, u1);  X[4] = csub(u0, u1);
    X[2] = cadd(u2, u3);  X[6] = csub(u2, u3);
    float2 v0 = cadd(d0, d2t), v2 = csub(d0, d2t);
    float2 v1 = cadd(d1t, d3t);
    float2 v3t = csub(d1t, d3t);
    float2 v3 = make_float2(v3t.y, -v3t.x);
    X[1] = cadd(v0, v1);  X[5] = csub(v0, v1);
    X[3] = cadd(v2, v3);  X[7] = csub(v2, v3);
}

static __device__ __forceinline__ float gray01(float r, float g, float b) {
    return (r * 0.299f + g * 0.587f + b * 0.114f + 1.0f) * 0.5f;
}

// -------- K0: twiddle table init (fast float path) --------
__global__ void k_init() {
    int t = threadIdx.x;
    float s, c;
    sincospif((float)t * (1.0f / 256.0f), &s, &c);   // w^t = cos - i*sin
    g_tw[t] = make_float2(c, -s);
}

#define PADIDX(i) ((i) + ((i) >> 3))

// -------- K1: fused gray + row-FFT + transposed fp16 write --------
// 8 FFTs (8 consecutive image rows of one batch) per 512-thread block.
// Input read with .cs (streaming) so the 67MB g_Bf intermediate stays
// L2-resident for pass 2. Transpose tile held in fp16.
__global__ void __launch_bounds__(512) k_fft1(const float* __restrict__ gen,
                                              const float* __restrict__ tgt) {
    __shared__ float2 tw[512];
    __shared__ float2 buf[8][576];   // 4608 float2; tail reused as __half2 tile[512*9]

    int tid = threadIdx.x;
    tw[tid] = g_tw[tid];

    int f = tid >> 6;                 // FFT id within block (0..7)
    int j = tid & 63;                 // lane within FFT
    int b  = blockIdx.x >> 6;         // 64 blocks per batch
    int y0 = (blockIdx.x & 63) << 3;  // first image row of this block
    int y  = y0 + f;

    size_t gbase = (size_t)b * (3u * NPIX) + (size_t)y * NS;
    const float* gp = gen + gbase;
    const float* tp = tgt + gbase;

    float2 a[8], X[8];
    #pragma unroll
    for (int p = 0; p < 8; p++) {
        int x = p * 64 + j;
        float g0 = __ldcs(gp + x), g1 = __ldcs(gp + x + NPIX), g2 = __ldcs(gp + x + 2 * NPIX);
        float t0 = __ldcs(tp + x), t1 = __ldcs(tp + x + NPIX), t2 = __ldcs(tp + x + 2 * NPIX);
        a[p] = make_float2(gray01(g0, g1, g2), gray01(t0, t1, t2));
    }

    // stage 0 (L=1)
    dft8(a, X);
    #pragma unroll
    for (int q = 0; q < 8; q++) { int idx = j * 8 + q; buf[f][PADIDX(idx)] = X[q]; }
    __syncthreads();   // also covers twiddle table fill

    // stage 1 (L=8)
    #pragma unroll
    for (int p = 0; p < 8; p++) { int idx = p * 64 + j; a[p] = buf[f][PADIDX(idx)]; }
    __syncthreads();
    int k1 = j & 7, b1 = j >> 3;
    #pragma unroll
    for (int p = 1; p < 8; p++) a[p] = cmul(a[p], tw[(p * k1) << 3]);
    dft8(a, X);
    #pragma unroll
    for (int q = 0; q < 8; q++) { int idx = b1 * 64 + q * 8 + k1; buf[f][PADIDX(idx)] = X[q]; }
    __syncthreads();

    // stage 2 (L=64)
    #pragma unroll
    for (int p = 0; p < 8; p++) { int idx = p * 64 + j; a[p] = buf[f][PADIDX(idx)]; }
    __syncthreads();   // all buf reads done; safe to reuse as fp16 transpose tile
    #pragma unroll
    for (int p = 1; p < 8; p++) a[p] = cmul(a[p], tw[p * j]);
    dft8(a, X);

    // stage result into fp16 transpose tile: tile[u*9 + f]
    __half2* tile = (__half2*)&buf[0][0];
    #pragma unroll
    for (int q = 0; q < 8; q++) {
        int u = q * 64 + j;
        tile[u * 9 + f] = __floats2half2_rn(X[q].x, X[q].y);
    }
    __syncthreads();

    // coalesced transposed fp16 write: 8 consecutive y per u = 32B sector
    int yo = tid & 7;          // y offset within block
    int ub = tid >> 3;         // 0..63
    __half2* dst = g_Bf + (size_t)b * NPIX + y0 + yo;
    #pragma unroll
    for (int i = 0; i < 8; i++) {
        int u = ub + i * 64;
        dst[(size_t)u * NS] = tile[u * 9 + yo];
    }
}

// -------- K2: column FFT on conjugate-partner row pairs + fused PSD --------
// 256 threads, 2 row-pairs (4 row FFTs) per block. grid (128, NB).
// g_Bf read with .cs (last use; L2-resident from pass 1).
// Half-domain PSD via PSD(-k)=PSD(k). For non-self pairs the f=0 group keeps
// its row in REGISTERS (z1), and only f=1 stores res -> ~17% fewer smem ops.
__global__ void __launch_bounds__(256) k_fft2_psd() {
    __shared__ float2 tw[512];
    __shared__ float2 buf2[4][576];   // 18432 B; reused as res[4][512] (16384 B)
    __shared__ float  wsum[8];

    int tid = threadIdx.x;
    tw[tid] = g_tw[tid];
    tw[tid + 256] = g_tw[tid + 256];

    int s    = tid >> 7;           // sub-block (pair) 0..1
    int tid2 = tid & 127;
    int f    = tid2 >> 6;          // 0 or 1 within pair
    int j    = tid2 & 63;
    int b    = blockIdx.y;
    int v    = blockIdx.x * 2 + s; // 0..255
    int rA = v;
    int rB = (v == 0) ? 256 : 512 - v;
    int r  = f ? rB : rA;
    float2* buf = &buf2[s * 2 + f][0];
    float2* res = &buf2[0][0];     // res[(s*2+h)*512 + e]

    const __half2* rp = g_Bf + (size_t)b * NPIX + (size_t)r * NS;

    float2 a[8], X[8];
    #pragma unroll
    for (int p = 0; p < 8; p++) a[p] = __half22float2(__ldcs(rp + p * 64 + j));

    dft8(a, X);
    #pragma unroll
    for (int q = 0; q < 8; q++) { int idx = j * 8 + q; buf[PADIDX(idx)] = X[q]; }
    __syncthreads();

    #pragma unroll
    for (int p = 0; p < 8; p++) { int idx = p * 64 + j; a[p] = buf[PADIDX(idx)]; }
    __syncthreads();
    int k1 = j & 7, b1 = j >> 3;
    #pragma unroll
    for (int p = 1; p < 8; p++) a[p] = cmul(a[p], tw[(p * k1) << 3]);
    dft8(a, X);
    #pragma unroll
    for (int q = 0; q < 8; q++) { int idx = b1 * 64 + q * 8 + k1; buf[PADIDX(idx)] = X[q]; }
    __syncthreads();

    #pragma unroll
    for (int p = 0; p < 8; p++) { int idx = p * 64 + j; a[p] = buf[PADIDX(idx)]; }
    __syncthreads();   // all buf reads done; safe to overwrite as res
    #pragma unroll
    for (int p = 1; p < 8; p++) a[p] = cmul(a[p], tw[p * j]);
    dft8(a, X);

    // res store: f=1 always (partner row, read by f=0's PSD); f=0 only for the
    // self-paired block (v==0), whose PSD needs same-row smem access.
    if (f == 1 || v == 0) {
        #pragma unroll
        for (int q = 0; q < 8; q++) res[(s * 2 + f) * 512 + q * 64 + j] = X[q];
    }
    __syncthreads();

    bool lowA = (rA < 64) | (rA >= 448);
    bool lowB = (rB < 64) | (rB >= 448);

    float acc = 0.0f;
    if (v != 0) {
        // Half-domain over row rA, z1 from registers (f=0 group only).
        if (f == 0) {
            #pragma unroll
            for (int q = 0; q < 8; q++) {
                int e  = q * 64 + j;           // this thread's own element of rA
                int e2 = (512 - e) & 511;
                bool m1 = !(lowA & ((e  < 64) | (e  >= 448)));   // mask(rA, e)
                bool m2 = !(lowB & ((e2 < 64) | (e2 >= 448)));   // mask(rB, -e)
                int wi = (int)m1 + (int)m2;
                if (wi == 0) continue;

                float2 z1 = X[q];
                float2 z2 = res[(s * 2 + 1) * 512 + e2];

                float ra = 0.5f * (z1.x + z2.x), ia = 0.5f * (z1.y - z2.y);
                float rb = 0.5f * (z1.y + z2.y), ib = 0.5f * (z2.x - z1.x);
                float pa = fmaf(ra, ra, ia * ia) + 1e-10f;
                float pb = fmaf(rb, rb, ib * ib) + 1e-10f;
                acc += (float)wi * (__log2f(pa) - __log2f(pb));
            }
        }
    } else {
        // Self-paired rows (u=0 and u=256): full domain, partner within same row.
        #pragma unroll
        for (int it = 0; it < 8; it++) {
            int i = it * 128 + tid2;       // 0..1023 over the pair's 2 rows
            int h = i >> 9;                // 0 -> row rA, 1 -> row rB
            int e = i & 511;
            bool lowr = h ? lowB : lowA;
            bool lowe = (e < 64) | (e >= 448);
            if (lowr & lowe) continue;

            float2 z1 = res[(s * 2 + h) * 512 + e];
            float2 z2 = res[(s * 2 + h) * 512 + ((512 - e) & 511)];

            float ra = 0.5f * (z1.x + z2.x), ia = 0.5f * (z1.y - z2.y);
            float rb = 0.5f * (z1.y + z2.y), ib = 0.5f * (z2.x - z1.x);
            float pa = fmaf(ra, ra, ia * ia) + 1e-10f;
            float pb = fmaf(rb, rb, ib * ib) + 1e-10f;
            acc += __log2f(pa) - __log2f(pb);
        }
    }

    // warp reduce (fixed order -> deterministic), then 4 warps per sub-block
    #pragma unroll
    for (int o = 16; o > 0; o >>= 1) acc += __shfl_down_sync(0xFFFFFFFFu, acc, o);
    if ((tid & 31) == 0) wsum[tid >> 5] = acc;
    __syncthreads();
    if (tid < 2) {
        int ss = tid;
        float d = wsum[ss * 4] + wsum[ss * 4 + 1] + wsum[ss * 4 + 2] + wsum[ss * 4 + 3];
        g_part[b][blockIdx.x * 2 + ss] = d;   // no atomics -> deterministic
    }
}

// -------- K3: finalize (parallel, coalesced, deterministic) --------
__global__ void __launch_bounds__(1024) k_final(float* __restrict__ out) {
    int t = threadIdx.x;
    int b = t >> 4, i = t & 15;
    float s = 0.0f;
    #pragma unroll
    for (int k = 0; k < 16; k++) s += g_part[b][i + k * 16];

    __shared__ float sh[64][17];
    __shared__ float red[64];
    sh[b][i] = s;
    __syncthreads();

    if (t < 64) {
        float d = 0.0f;
        #pragma unroll
        for (int k = 0; k < 16; k++) d += sh[t][k];
        red[t] = fabsf(d);
    }
    __syncthreads();
    #pragma unroll
    for (int s2 = 32; s2 > 0; s2 >>= 1) {
        if (t < s2) red[t] += red[t + s2];
        __syncthreads();
    }
    if (t == 0) out[0] = red[0] * (0.30102999566398119521f / (HF_COUNT * 64.0f));
}

// -------- launch --------
extern "C" void kernel_launch(void* const* d_in, const int* in_sizes, int n_in,
                              void* d_out, int out_size) {
    const float* gen = (const float*)d_in[0];
    const float* tgt = (const float*)d_in[1];
    float* out = (float*)d_out;
    (void)in_sizes; (void)n_in; (void)out_size;

    k_init<<<1, 512>>>();
    k_fft1<<<NB * 64, 512>>>(gen, tgt);        // fused gray + row FFT + transpose
    {
        dim3 g(128, NB);
        k_fft2_psd<<<g, 256>>>();              // column FFT + fused PSD (register z1)
    }
    k_final<<<1, 1024>>>(out);
}

// round 15
// speedup vs baseline: 1.5223x; 1.5223x over previous
#include <cuda_runtime.h>
#include <cuda_fp16.h>
#include <math.h>

// Problem constants
#define NB 64
#define NS 512
#define NPIX (NS * NS)          // 262144
#define HF_COUNT 245760.0f      // 512*512 - 128*128

// -------- scratch (device globals; no allocation allowed) --------
__device__ __half2 g_Bf[NB * NPIX];  // 67 MB: pass-1 output (fp16 complex), TRANSPOSED
__device__ float2  g_tw[512];        // twiddles w^k = exp(-2*pi*i*k/512)
__device__ float   g_part[NB][256];  // per-(batch, v-pair) partial sums (deterministic)

// -------- complex helpers --------
static __device__ __forceinline__ float2 cadd(float2 a, float2 b) { return make_float2(a.x + b.x, a.y + b.y); }
static __device__ __forceinline__ float2 csub(float2 a, float2 b) { return make_float2(a.x - b.x, a.y - b.y); }
static __device__ __forceinline__ float2 cmul(float2 a, float2 w) {
    return make_float2(fmaf(a.x, w.x, -a.y * w.y), fmaf(a.x, w.y, a.y * w.x));
}

// DFT-8 (DIF internally, output in natural order X[0..7])
static __device__ __forceinline__ void dft8(const float2 a[8], float2 X[8]) {
    const float r = 0.70710678118654752440f;
    float2 s0 = cadd(a[0], a[4]), d0 = csub(a[0], a[4]);
    float2 s1 = cadd(a[1], a[5]), d1 = csub(a[1], a[5]);
    float2 s2 = cadd(a[2], a[6]), d2 = csub(a[2], a[6]);
    float2 s3 = cadd(a[3], a[7]), d3 = csub(a[3], a[7]);
    float2 d1t = make_float2(r * (d1.x + d1.y), r * (d1.y - d1.x));
    float2 d2t = make_float2(d2.y, -d2.x);
    float2 d3t = make_float2(r * (d3.y - d3.x), -r * (d3.x + d3.y));
    float2 u0 = cadd(s0, s2), u2 = csub(s0, s2);
    float2 u1 = cadd(s1, s3);
    float2 u3t = csub(s1, s3);
    float2 u3 = make_float2(u3t.y, -u3t.x);
    X[0] = cadd(u0, u1);  X[4] = csub(u0, u1);
    X[2] = cadd(u2, u3);  X[6] = csub(u2, u3);
    float2 v0 = cadd(d0, d2t), v2 = csub(d0, d2t);
    float2 v1 = cadd(d1t, d3t);
    float2 v3t = csub(d1t, d3t);
    float2 v3 = make_float2(v3t.y, -v3t.x);
    X[1] = cadd(v0, v1);  X[5] = csub(v0, v1);
    X[3] = cadd(v2, v3);  X[7] = csub(v2, v3);
}

static __device__ __forceinline__ float gray01(float r, float g, float b) {
    return (r * 0.299f + g * 0.587f + b * 0.114f + 1.0f) * 0.5f;
}

// -------- K0: twiddle table init (fast float path) --------
__global__ void k_init() {
    int t = threadIdx.x;
    float s, c;
    sincospif((float)t * (1.0f / 256.0f), &s, &c);   // w^t = cos - i*sin
    g_tw[t] = make_float2(c, -s);
}

#define PADIDX(i) ((i) + ((i) >> 3))

// -------- K1: fused gray + row-FFT + transposed fp16 write --------
// 8 FFTs (8 consecutive image rows of one batch) per 512-thread block.
// Input read with .cs (streaming, evict-first) so the 67MB g_Bf intermediate
// stays L2-resident for pass 2. Transpose tile held in fp16 (halves its
// crossbar traffic; conversion point is value-identical to converting at store).
__global__ void __launch_bounds__(512) k_fft1(const float* __restrict__ gen,
                                              const float* __restrict__ tgt) {
    __shared__ float2 tw[512];
    __shared__ float2 buf[8][576];   // 4608 float2; tail reused as __half2 tile[512*9]

    int tid = threadIdx.x;
    tw[tid] = g_tw[tid];

    int f = tid >> 6;                 // FFT id within block (0..7)
    int j = tid & 63;                 // lane within FFT
    int b  = blockIdx.x >> 6;         // 64 blocks per batch
    int y0 = (blockIdx.x & 63) << 3;  // first image row of this block
    int y  = y0 + f;

    size_t gbase = (size_t)b * (3u * NPIX) + (size_t)y * NS;
    const float* gp = gen + gbase;
    const float* tp = tgt + gbase;

    float2 a[8], X[8];
    #pragma unroll
    for (int p = 0; p < 8; p++) {
        int x = p * 64 + j;
        float g0 = __ldcs(gp + x), g1 = __ldcs(gp + x + NPIX), g2 = __ldcs(gp + x + 2 * NPIX);
        float t0 = __ldcs(tp + x), t1 = __ldcs(tp + x + NPIX), t2 = __ldcs(tp + x + 2 * NPIX);
        a[p] = make_float2(gray01(g0, g1, g2), gray01(t0, t1, t2));
    }

    // stage 0 (L=1)
    dft8(a, X);
    #pragma unroll
    for (int q = 0; q < 8; q++) { int idx = j * 8 + q; buf[f][PADIDX(idx)] = X[q]; }
    __syncthreads();   // also covers twiddle table fill

    // stage 1 (L=8)
    #pragma unroll
    for (int p = 0; p < 8; p++) { int idx = p * 64 + j; a[p] = buf[f][PADIDX(idx)]; }
    __syncthreads();
    int k1 = j & 7, b1 = j >> 3;
    #pragma unroll
    for (int p = 1; p < 8; p++) a[p] = cmul(a[p], tw[(p * k1) << 3]);
    dft8(a, X);
    #pragma unroll
    for (int q = 0; q < 8; q++) { int idx = b1 * 64 + q * 8 + k1; buf[f][PADIDX(idx)] = X[q]; }
    __syncthreads();

    // stage 2 (L=64)
    #pragma unroll
    for (int p = 0; p < 8; p++) { int idx = p * 64 + j; a[p] = buf[f][PADIDX(idx)]; }
    __syncthreads();   // all buf reads done; safe to reuse as fp16 transpose tile
    #pragma unroll
    for (int p = 1; p < 8; p++) a[p] = cmul(a[p], tw[p * j]);
    dft8(a, X);

    // stage result into fp16 transpose tile: tile[u*9 + f]
    __half2* tile = (__half2*)&buf[0][0];
    #pragma unroll
    for (int q = 0; q < 8; q++) {
        int u = q * 64 + j;
        tile[u * 9 + f] = __floats2half2_rn(X[q].x, X[q].y);
    }
    __syncthreads();

    // coalesced transposed fp16 write: 8 consecutive y per u = 32B sector
    int yo = tid & 7;          // y offset within block
    int ub = tid >> 3;         // 0..63
    __half2* dst = g_Bf + (size_t)b * NPIX + y0 + yo;
    #pragma unroll
    for (int i = 0; i < 8; i++) {
        int u = ub + i * 64;
        dst[(size_t)u * NS] = tile[u * 9 + yo];
    }
}

// -------- K2: column FFT on conjugate-partner row pairs + fused PSD --------
// 256 threads, 2 row-pairs (4 row FFTs) per block. grid (128, NB).
// g_Bf read with .cs (last use; expected L2-resident from pass 1).
// PSD uses PSD(-k)=PSD(k) (real inputs): non-self pairs evaluate only row rA's
// 512 elements, weighting each by (mask(k) + mask(-k)). Mask box is [-64,63],
// NOT negation-symmetric at +/-64 -> both mask bits evaluated explicitly.
__global__ void __launch_bounds__(256) k_fft2_psd() {
    __shared__ float2 tw[512];
    __shared__ float2 buf2[4][576];   // 18432 B; reused as res[4][512] (16384 B)
    __shared__ float  wsum[8];

    int tid = threadIdx.x;
    tw[tid] = g_tw[tid];
    tw[tid + 256] = g_tw[tid + 256];

    int s    = tid >> 7;           // sub-block (pair) 0..1
    int tid2 = tid & 127;
    int f    = tid2 >> 6;          // 0 or 1 within pair
    int j    = tid2 & 63;
    int b    = blockIdx.y;
    int v    = blockIdx.x * 2 + s; // 0..255
    int rA = v;
    int rB = (v == 0) ? 256 : 512 - v;
    int r  = f ? rB : rA;
    float2* buf = &buf2[s * 2 + f][0];
    float2* res = &buf2[0][0];     // res[(s*2+h)*512 + e]

    const __half2* rp = g_Bf + (size_t)b * NPIX + (size_t)r * NS;

    float2 a[8], X[8];
    #pragma unroll
    for (int p = 0; p < 8; p++) a[p] = __half22float2(__ldcs(rp + p * 64 + j));

    dft8(a, X);
    #pragma unroll
    for (int q = 0; q < 8; q++) { int idx = j * 8 + q; buf[PADIDX(idx)] = X[q]; }
    __syncthreads();

    #pragma unroll
    for (int p = 0; p < 8; p++) { int idx = p * 64 + j; a[p] = buf[PADIDX(idx)]; }
    __syncthreads();
    int k1 = j & 7, b1 = j >> 3;
    #pragma unroll
    for (int p = 1; p < 8; p++) a[p] = cmul(a[p], tw[(p * k1) << 3]);
    dft8(a, X);
    #pragma unroll
    for (int q = 0; q < 8; q++) { int idx = b1 * 64 + q * 8 + k1; buf[PADIDX(idx)] = X[q]; }
    __syncthreads();

    #pragma unroll
    for (int p = 0; p < 8; p++) { int idx = p * 64 + j; a[p] = buf[PADIDX(idx)]; }
    __syncthreads();   // all buf reads done; safe to overwrite as res
    #pragma unroll
    for (int p = 1; p < 8; p++) a[p] = cmul(a[p], tw[p * j]);
    dft8(a, X);
    #pragma unroll
    for (int q = 0; q < 8; q++) res[(s * 2 + f) * 512 + q * 64 + j] = X[q];
    __syncthreads();

    bool lowA = (rA < 64) | (rA >= 448);
    bool lowB = (rB < 64) | (rB >= 448);

    float acc = 0.0f;
    if (v != 0) {
        // Half-domain: element (rA, e) with partner (rB, (512-e)&511).
        #pragma unroll
        for (int it = 0; it < 4; it++) {
            int e  = it * 128 + tid2;      // 0..511
            int e2 = (512 - e) & 511;
            bool m1 = !(lowA & ((e  < 64) | (e  >= 448)));   // mask(rA, e)
            bool m2 = !(lowB & ((e2 < 64) | (e2 >= 448)));   // mask(rB, -e)
            int wi = (int)m1 + (int)m2;
            if (wi == 0) continue;

            float2 z1 = res[(s * 2 + 0) * 512 + e];
            float2 z2 = res[(s * 2 + 1) * 512 + e2];

            float ra = 0.5f * (z1.x + z2.x), ia = 0.5f * (z1.y - z2.y);
            float rb = 0.5f * (z1.y + z2.y), ib = 0.5f * (z2.x - z1.x);
            float pa = fmaf(ra, ra, ia * ia) + 1e-10f;
            float pb = fmaf(rb, rb, ib * ib) + 1e-10f;
            acc += (float)wi * (__log2f(pa) - __log2f(pb));
        }
    } else {
        // Self-paired rows (u=0 and u=256): full domain, partner within same row.
        #pragma unroll
        for (int it = 0; it < 8; it++) {
            int i = it * 128 + tid2;       // 0..1023 over the pair's 2 rows
            int h = i >> 9;                // 0 -> row rA, 1 -> row rB
            int e = i & 511;
            bool lowr = h ? lowB : lowA;
            bool lowe = (e < 64) | (e >= 448);
            if (lowr & lowe) continue;

            float2 z1 = res[(s * 2 + h) * 512 + e];
            float2 z2 = res[(s * 2 + h) * 512 + ((512 - e) & 511)];

            float ra = 0.5f * (z1.x + z2.x), ia = 0.5f * (z1.y - z2.y);
            float rb = 0.5f * (z1.y + z2.y), ib = 0.5f * (z2.x - z1.x);
            float pa = fmaf(ra, ra, ia * ia) + 1e-10f;
            float pb = fmaf(rb, rb, ib * ib) + 1e-10f;
            acc += __log2f(pa) - __log2f(pb);
        }
    }

    // warp reduce (fixed order -> deterministic), then 4 warps per sub-block
    #pragma unroll
    for (int o = 16; o > 0; o >>= 1) acc += __shfl_down_sync(0xFFFFFFFFu, acc, o);
    if ((tid & 31) == 0) wsum[tid >> 5] = acc;
    __syncthreads();
    if (tid < 2) {
        int ss = tid;
        float d = wsum[ss * 4] + wsum[ss * 4 + 1] + wsum[ss * 4 + 2] + wsum[ss * 4 + 3];
        g_part[b][blockIdx.x * 2 + ss] = d;   // no atomics -> deterministic
    }
}

// -------- K3: finalize (parallel, coalesced, deterministic) --------
__global__ void __launch_bounds__(1024) k_final(float* __restrict__ out) {
    int t = threadIdx.x;
    int b = t >> 4, i = t & 15;
    float s = 0.0f;
    #pragma unroll
    for (int k = 0; k < 16; k++) s += g_part[b][i + k * 16];

    __shared__ float sh[64][17];
    __shared__ float red[64];
    sh[b][i] = s;
    __syncthreads();

    if (t < 64) {
        float d = 0.0f;
        #pragma unroll
        for (int k = 0; k < 16; k++) d += sh[t][k];
        red[t] = fabsf(d);
    }
    __syncthreads();
    #pragma unroll
    for (int s2 = 32; s2 > 0; s2 >>= 1) {
        if (t < s2) red[t] += red[t + s2];
        __syncthreads();
    }
    if (t == 0) out[0] = red[0] * (0.30102999566398119521f / (HF_COUNT * 64.0f));
}

// -------- launch --------
extern "C" void kernel_launch(void* const* d_in, const int* in_sizes, int n_in,
                              void* d_out, int out_size) {
    const float* gen = (const float*)d_in[0];
    const float* tgt = (const float*)d_in[1];
    float* out = (float*)d_out;
    (void)in_sizes; (void)n_in; (void)out_size;

    k_init<<<1, 512>>>();
    k_fft1<<<NB * 64, 512>>>(gen, tgt);        // fused gray + row FFT + transpose
    {
        dim3 g(128, NB);
        k_fft2_psd<<<g, 256>>>();              // column FFT + fused PSD (symmetry-halved)
    }
    k_final<<<1, 1024>>>(out);
}

// round 16
// speedup vs baseline: 1.5434x; 1.0139x over previous
#include <cuda_runtime.h>
#include <cuda_fp16.h>
#include <math.h>

// Problem constants
#define NB 64
#define NS 512
#define NPIX (NS * NS)          // 262144
#define HF_COUNT 245760.0f      // 512*512 - 128*128

// -------- scratch (device globals; no allocation allowed) --------
__device__ __half2 g_Bf[NB * NPIX];  // 67 MB: pass-1 output (fp16 complex), TRANSPOSED
__device__ float2  g_tw[512];        // twiddles; written by fft1 block 0, read by fft2
__device__ float   g_part[NB][256];  // per-(batch, v-pair) partial sums (deterministic)

// -------- complex helpers --------
static __device__ __forceinline__ float2 cadd(float2 a, float2 b) { return make_float2(a.x + b.x, a.y + b.y); }
static __device__ __forceinline__ float2 csub(float2 a, float2 b) { return make_float2(a.x - b.x, a.y - b.y); }
static __device__ __forceinline__ float2 cmul(float2 a, float2 w) {
    return make_float2(fmaf(a.x, w.x, -a.y * w.y), fmaf(a.x, w.y, a.y * w.x));
}

// DFT-8 (DIF internally, output in natural order X[0..7])
static __device__ __forceinline__ void dft8(const float2 a[8], float2 X[8]) {
    const float r = 0.70710678118654752440f;
    float2 s0 = cadd(a[0], a[4]), d0 = csub(a[0], a[4]);
    float2 s1 = cadd(a[1], a[5]), d1 = csub(a[1], a[5]);
    float2 s2 = cadd(a[2], a[6]), d2 = csub(a[2], a[6]);
    float2 s3 = cadd(a[3], a[7]), d3 = csub(a[3], a[7]);
    float2 d1t = make_float2(r * (d1.x + d1.y), r * (d1.y - d1.x));
    float2 d2t = make_float2(d2.y, -d2.x);
    float2 d3t = make_float2(r * (d3.y - d3.x), -r * (d3.x + d3.y));
    float2 u0 = cadd(s0, s2), u2 = csub(s0, s2);
    float2 u1 = cadd(s1, s3);
    float2 u3t = csub(s1, s3);
    float2 u3 = make_float2(u3t.y, -u3t.x);
    X[0] = cadd(u0, u1);  X[4] = csub(u0, u1);
    X[2] = cadd(u2, u3);  X[6] = csub(u2, u3);
    float2 v0 = cadd(d0, d2t), v2 = csub(d0, d2t);
    float2 v1 = cadd(d1t, d3t);
    float2 v3t = csub(d1t, d3t);
    float2 v3 = make_float2(v3t.y, -v3t.x);
    X[1] = cadd(v0, v1);  X[5] = csub(v0, v1);
    X[3] = cadd(v2, v3);  X[7] = csub(v2, v3);
}

static __device__ __forceinline__ float gray01(float r, float g, float b) {
    return (r * 0.299f + g * 0.587f + b * 0.114f + 1.0f) * 0.5f;
}

// twiddle w^k = exp(-2*pi*i*k/512) = cos(pi*k/256) - i*sin(pi*k/256)
static __device__ __forceinline__ float2 twiddle(int k) {
    float s, c;
    sincospif((float)k * (1.0f / 256.0f), &s, &c);
    return make_float2(c, -s);
}

#define PADIDX(i) ((i) + ((i) >> 3))

// -------- K1: fused gray + row-FFT + transposed fp16 write --------
// 8 FFTs (8 consecutive image rows of one batch) per 512-thread block.
// Twiddles computed in-block via sincospif (fft1 is memory-bound; MUFU is idle).
// Block 0 publishes the table to g_tw for fft2 (kernel-boundary visibility).
// Input read with .cs (streaming) so the 67MB g_Bf intermediate stays
// L2-resident for pass 2. Transpose tile held in fp16.
__global__ void __launch_bounds__(512) k_fft1(const float* __restrict__ gen,
                                              const float* __restrict__ tgt) {
    __shared__ float2 tw[512];
    __shared__ float2 buf[8][576];   // 4608 float2; tail reused as __half2 tile[512*9]

    int tid = threadIdx.x;
    {
        float2 w = twiddle(tid);
        tw[tid] = w;
        if (blockIdx.x == 0) g_tw[tid] = w;   // publish for fft2 (values bit-identical)
    }

    int f = tid >> 6;                 // FFT id within block (0..7)
    int j = tid & 63;                 // lane within FFT
    int b  = blockIdx.x >> 6;         // 64 blocks per batch
    int y0 = (blockIdx.x & 63) << 3;  // first image row of this block
    int y  = y0 + f;

    size_t gbase = (size_t)b * (3u * NPIX) + (size_t)y * NS;
    const float* gp = gen + gbase;
    const float* tp = tgt + gbase;

    float2 a[8], X[8];
    #pragma unroll
    for (int p = 0; p < 8; p++) {
        int x = p * 64 + j;
        float g0 = __ldcs(gp + x), g1 = __ldcs(gp + x + NPIX), g2 = __ldcs(gp + x + 2 * NPIX);
        float t0 = __ldcs(tp + x), t1 = __ldcs(tp + x + NPIX), t2 = __ldcs(tp + x + 2 * NPIX);
        a[p] = make_float2(gray01(g0, g1, g2), gray01(t0, t1, t2));
    }

    // stage 0 (L=1)
    dft8(a, X);
    #pragma unroll
    for (int q = 0; q < 8; q++) { int idx = j * 8 + q; buf[f][PADIDX(idx)] = X[q]; }
    __syncthreads();   // also covers twiddle fill

    // stage 1 (L=8)
    #pragma unroll
    for (int p = 0; p < 8; p++) { int idx = p * 64 + j; a[p] = buf[f][PADIDX(idx)]; }
    __syncthreads();
    int k1 = j & 7, b1 = j >> 3;
    #pragma unroll
    for (int p = 1; p < 8; p++) a[p] = cmul(a[p], tw[(p * k1) << 3]);
    dft8(a, X);
    #pragma unroll
    for (int q = 0; q < 8; q++) { int idx = b1 * 64 + q * 8 + k1; buf[f][PADIDX(idx)] = X[q]; }
    __syncthreads();

    // stage 2 (L=64)
    #pragma unroll
    for (int p = 0; p < 8; p++) { int idx = p * 64 + j; a[p] = buf[f][PADIDX(idx)]; }
    __syncthreads();   // all buf reads done; safe to reuse as fp16 transpose tile
    #pragma unroll
    for (int p = 1; p < 8; p++) a[p] = cmul(a[p], tw[p * j]);
    dft8(a, X);

    // stage result into fp16 transpose tile: tile[u*9 + f]
    __half2* tile = (__half2*)&buf[0][0];
    #pragma unroll
    for (int q = 0; q < 8; q++) {
        int u = q * 64 + j;
        tile[u * 9 + f] = __floats2half2_rn(X[q].x, X[q].y);
    }
    __syncthreads();

    // coalesced transposed fp16 write: 8 consecutive y per u = 32B sector
    int yo = tid & 7;          // y offset within block
    int ub = tid >> 3;         // 0..63
    __half2* dst = g_Bf + (size_t)b * NPIX + y0 + yo;
    #pragma unroll
    for (int i = 0; i < 8; i++) {
        int u = ub + i * 64;
        dst[(size_t)u * NS] = tile[u * 9 + yo];
    }
}

// -------- K2: column FFT on conjugate-partner row pairs + fused PSD --------
// 256 threads, 2 row-pairs (4 row FFTs) per block. grid (128, NB).
// Twiddles from the g_tw table (fft2's MUFU is loaded by __log2f; table wins).
// g_Bf read with .cs (last use; expected L2-resident from pass 1).
// PSD uses PSD(-k)=PSD(k) (real inputs): non-self pairs evaluate only row rA's
// 512 elements, weighting each by (mask(k) + mask(-k)). Mask box is [-64,63],
// NOT negation-symmetric at +/-64 -> both mask bits evaluated explicitly.
__global__ void __launch_bounds__(256) k_fft2_psd() {
    __shared__ float2 tw[512];
    __shared__ float2 buf2[4][576];   // 18432 B; reused as res[4][512] (16384 B)
    __shared__ float  wsum[8];

    int tid = threadIdx.x;
    tw[tid] = g_tw[tid];
    tw[tid + 256] = g_tw[tid + 256];

    int s    = tid >> 7;           // sub-block (pair) 0..1
    int tid2 = tid & 127;
    int f    = tid2 >> 6;          // 0 or 1 within pair
    int j    = tid2 & 63;
    int b    = blockIdx.y;
    int v    = blockIdx.x * 2 + s; // 0..255
    int rA = v;
    int rB = (v == 0) ? 256 : 512 - v;
    int r  = f ? rB : rA;
    float2* buf = &buf2[s * 2 + f][0];
    float2* res = &buf2[0][0];     // res[(s*2+h)*512 + e]

    const __half2* rp = g_Bf + (size_t)b * NPIX + (size_t)r * NS;

    float2 a[8], X[8];
    #pragma unroll
    for (int p = 0; p < 8; p++) a[p] = __half22float2(__ldcs(rp + p * 64 + j));

    dft8(a, X);
    #pragma unroll
    for (int q = 0; q < 8; q++) { int idx = j * 8 + q; buf[PADIDX(idx)] = X[q]; }
    __syncthreads();

    #pragma unroll
    for (int p = 0; p < 8; p++) { int idx = p * 64 + j; a[p] = buf[PADIDX(idx)]; }
    __syncthreads();
    int k1 = j & 7, b1 = j >> 3;
    #pragma unroll
    for (int p = 1; p < 8; p++) a[p] = cmul(a[p], tw[(p * k1) << 3]);
    dft8(a, X);
    #pragma unroll
    for (int q = 0; q < 8; q++) { int idx = b1 * 64 + q * 8 + k1; buf[PADIDX(idx)] = X[q]; }
    __syncthreads();

    #pragma unroll
    for (int p = 0; p < 8; p++) { int idx = p * 64 + j; a[p] = buf[PADIDX(idx)]; }
    __syncthreads();   // all buf reads done; safe to overwrite as res
    #pragma unroll
    for (int p = 1; p < 8; p++) a[p] = cmul(a[p], tw[p * j]);
    dft8(a, X);
    #pragma unroll
    for (int q = 0; q < 8; q++) res[(s * 2 + f) * 512 + q * 64 + j] = X[q];
    __syncthreads();

    bool lowA = (rA < 64) | (rA >= 448);
    bool lowB = (rB < 64) | (rB >= 448);

    float acc = 0.0f;
    if (v != 0) {
        // Half-domain: element (rA, e) with partner (rB, (512-e)&511).
        #pragma unroll
        for (int it = 0; it < 4; it++) {
            int e  = it * 128 + tid2;      // 0..511
            int e2 = (512 - e) & 511;
            bool m1 = !(lowA & ((e  < 64) | (e  >= 448)));   // mask(rA, e)
            bool m2 = !(lowB & ((e2 < 64) | (e2 >= 448)));   // mask(rB, -e)
            int wi = (int)m1 + (int)m2;
            if (wi == 0) continue;

            float2 z1 = res[(s * 2 + 0) * 512 + e];
            float2 z2 = res[(s * 2 + 1) * 512 + e2];

            float ra = 0.5f * (z1.x + z2.x), ia = 0.5f * (z1.y - z2.y);
            float rb = 0.5f * (z1.y + z2.y), ib = 0.5f * (z2.x - z1.x);
            float pa = fmaf(ra, ra, ia * ia) + 1e-10f;
            float pb = fmaf(rb, rb, ib * ib) + 1e-10f;
            acc += (float)wi * (__log2f(pa) - __log2f(pb));
        }
    } else {
        // Self-paired rows (u=0 and u=256): full domain, partner within same row.
        #pragma unroll
        for (int it = 0; it < 8; it++) {
            int i = it * 128 + tid2;       // 0..1023 over the pair's 2 rows
            int h = i >> 9;                // 0 -> row rA, 1 -> row rB
            int e = i & 511;
            bool lowr = h ? lowB : lowA;
            bool lowe = (e < 64) | (e >= 448);
            if (lowr & lowe) continue;

            float2 z1 = res[(s * 2 + h) * 512 + e];
            float2 z2 = res[(s * 2 + h) * 512 + ((512 - e) & 511)];

            float ra = 0.5f * (z1.x + z2.x), ia = 0.5f * (z1.y - z2.y);
            float rb = 0.5f * (z1.y + z2.y), ib = 0.5f * (z2.x - z1.x);
            float pa = fmaf(ra, ra, ia * ia) + 1e-10f;
            float pb = fmaf(rb, rb, ib * ib) + 1e-10f;
            acc += __log2f(pa) - __log2f(pb);
        }
    }

    // warp reduce (fixed order -> deterministic), then 4 warps per sub-block
    #pragma unroll
    for (int o = 16; o > 0; o >>= 1) acc += __shfl_down_sync(0xFFFFFFFFu, acc, o);
    if ((tid & 31) == 0) wsum[tid >> 5] = acc;
    __syncthreads();
    if (tid < 2) {
        int ss = tid;
        float d = wsum[ss * 4] + wsum[ss * 4 + 1] + wsum[ss * 4 + 2] + wsum[ss * 4 + 3];
        g_part[b][blockIdx.x * 2 + ss] = d;   // no atomics -> deterministic
    }
}

// -------- K3: finalize (parallel, coalesced, deterministic) --------
__global__ void __launch_bounds__(1024) k_final(float* __restrict__ out) {
    int t = threadIdx.x;
    int b = t >> 4, i = t & 15;
    float s = 0.0f;
    #pragma unroll
    for (int k = 0; k < 16; k++) s += g_part[b][i + k * 16];

    __shared__ float sh[64][17];
    __shared__ float red[64];
    sh[b][i] = s;
    __syncthreads();

    if (t < 64) {
        float d = 0.0f;
        #pragma unroll
        for (int k = 0; k < 16; k++) d += sh[t][k];
        red[t] = fabsf(d);
    }
    __syncthreads();
    #pragma unroll
    for (int s2 = 32; s2 > 0; s2 >>= 1) {
        if (t < s2) red[t] += red[t + s2];
        __syncthreads();
    }
    if (t == 0) out[0] = red[0] * (0.30102999566398119521f / (HF_COUNT * 64.0f));
}

// -------- launch --------
extern "C" void kernel_launch(void* const* d_in, const int* in_sizes, int n_in,
                              void* d_out, int out_size) {
    const float* gen = (const float*)d_in[0];
    const float* tgt = (const float*)d_in[1];
    float* out = (float*)d_out;
    (void)in_sizes; (void)n_in; (void)out_size;

    k_fft1<<<NB * 64, 512>>>(gen, tgt);        // fused gray + row FFT + transpose (+ twiddle publish)
    {
        dim3 g(128, NB);
        k_fft2_psd<<<g, 256>>>();              // column FFT + fused PSD (symmetry-halved)
    }
    k_final<<<1, 1024>>>(out);
}

// round 17
// speedup vs baseline: 1.5494x; 1.0039x over previous
#include <cuda_runtime.h>
#include <cuda_fp16.h>
#include <math.h>

// Problem constants
#define NB 64
#define NS 512
#define NPIX (NS * NS)          // 262144
#define HF_COUNT 245760.0f      // 512*512 - 128*128

// -------- scratch (device globals; no allocation allowed) --------
__device__ __half2 g_Bf[NB * NPIX];  // 67 MB: pass-1 output (fp16 complex), TRANSPOSED
__device__ float2  g_tw[512];        // twiddles; written by fft1 block 0, read by fft2
__device__ float   g_part[NB][256];  // per-(batch, v-pair) partial sums (deterministic)

// -------- complex helpers --------
static __device__ __forceinline__ float2 cadd(float2 a, float2 b) { return make_float2(a.x + b.x, a.y + b.y); }
static __device__ __forceinline__ float2 csub(float2 a, float2 b) { return make_float2(a.x - b.x, a.y - b.y); }
static __device__ __forceinline__ float2 cmul(float2 a, float2 w) {
    return make_float2(fmaf(a.x, w.x, -a.y * w.y), fmaf(a.x, w.y, a.y * w.x));
}

// DFT-8 (DIF internally, output in natural order X[0..7])
static __device__ __forceinline__ void dft8(const float2 a[8], float2 X[8]) {
    const float r = 0.70710678118654752440f;
    float2 s0 = cadd(a[0], a[4]), d0 = csub(a[0], a[4]);
    float2 s1 = cadd(a[1], a[5]), d1 = csub(a[1], a[5]);
    float2 s2 = cadd(a[2], a[6]), d2 = csub(a[2], a[6]);
    float2 s3 = cadd(a[3], a[7]), d3 = csub(a[3], a[7]);
    float2 d1t = make_float2(r * (d1.x + d1.y), r * (d1.y - d1.x));
    float2 d2t = make_float2(d2.y, -d2.x);
    float2 d3t = make_float2(r * (d3.y - d3.x), -r * (d3.x + d3.y));
    float2 u0 = cadd(s0, s2), u2 = csub(s0, s2);
    float2 u1 = cadd(s1, s3);
    float2 u3t = csub(s1, s3);
    float2 u3 = make_float2(u3t.y, -u3t.x);
    X[0] = cadd(u0, u1);  X[4] = csub(u0, u1);
    X[2] = cadd(u2, u3);  X[6] = csub(u2, u3);
    float2 v0 = cadd(d0, d2t), v2 = csub(d0, d2t);
    float2 v1 = cadd(d1t, d3t);
    float2 v3t = csub(d1t, d3t);
    float2 v3 = make_float2(v3t.y, -v3t.x);
    X[1] = cadd(v0, v1);  X[5] = csub(v0, v1);
    X[3] = cadd(v2, v3);  X[7] = csub(v2, v3);
}

static __device__ __forceinline__ float gray01(float r, float g, float b) {
    return (r * 0.299f + g * 0.587f + b * 0.114f + 1.0f) * 0.5f;
}

// twiddle w^k = exp(-2*pi*i*k/512) = cos(pi*k/256) - i*sin(pi*k/256)
static __device__ __forceinline__ float2 twiddle(int k) {
    float s, c;
    sincospif((float)k * (1.0f / 256.0f), &s, &c);
    return make_float2(c, -s);
}

#define PADIDX(i) ((i) + ((i) >> 3))

// -------- K1: fused gray + row-FFT + transposed fp16 write --------
// 8 FFTs (8 consecutive image rows of one batch) per 512-thread block.
// Stage-exchange buffers held in fp16 (__half2 per complex): halves the L1
// crossbar wavefronts of the exchanges, fft1's binding resource. Intermediates
// are <= ~64 in magnitude -> no fp16 overflow; added quantization is zero-mean.
// Twiddles computed in-block via sincospif; block 0 publishes g_tw for fft2.
// Input read with .cs (streaming) so the 67MB g_Bf stays L2-resident.
__global__ void __launch_bounds__(512) k_fft1(const float* __restrict__ gen,
                                              const float* __restrict__ tgt) {
    __shared__ float2  tw[512];
    __shared__ __half2 buf[8][576];   // fp16 exchange; reused as tile[512*9] at the end

    int tid = threadIdx.x;
    {
        float2 w = twiddle(tid);
        tw[tid] = w;
        if (blockIdx.x == 0) g_tw[tid] = w;   // publish for fft2 (values bit-identical)
    }

    int f = tid >> 6;                 // FFT id within block (0..7)
    int j = tid & 63;                 // lane within FFT
    int b  = blockIdx.x >> 6;         // 64 blocks per batch
    int y0 = (blockIdx.x & 63) << 3;  // first image row of this block
    int y  = y0 + f;

    size_t gbase = (size_t)b * (3u * NPIX) + (size_t)y * NS;
    const float* gp = gen + gbase;
    const float* tp = tgt + gbase;

    float2 a[8], X[8];
    #pragma unroll
    for (int p = 0; p < 8; p++) {
        int x = p * 64 + j;
        float g0 = __ldcs(gp + x), g1 = __ldcs(gp + x + NPIX), g2 = __ldcs(gp + x + 2 * NPIX);
        float t0 = __ldcs(tp + x), t1 = __ldcs(tp + x + NPIX), t2 = __ldcs(tp + x + 2 * NPIX);
        a[p] = make_float2(gray01(g0, g1, g2), gray01(t0, t1, t2));
    }

    // stage 0 (L=1)
    dft8(a, X);
    #pragma unroll
    for (int q = 0; q < 8; q++) {
        int idx = j * 8 + q;
        buf[f][PADIDX(idx)] = __floats2half2_rn(X[q].x, X[q].y);
    }
    __syncthreads();   // also covers twiddle fill

    // stage 1 (L=8)
    #pragma unroll
    for (int p = 0; p < 8; p++) { int idx = p * 64 + j; a[p] = __half22float2(buf[f][PADIDX(idx)]); }
    __syncthreads();
    int k1 = j & 7, b1 = j >> 3;
    #pragma unroll
    for (int p = 1; p < 8; p++) a[p] = cmul(a[p], tw[(p * k1) << 3]);
    dft8(a, X);
    #pragma unroll
    for (int q = 0; q < 8; q++) {
        int idx = b1 * 64 + q * 8 + k1;
        buf[f][PADIDX(idx)] = __floats2half2_rn(X[q].x, X[q].y);
    }
    __syncthreads();

    // stage 2 (L=64)
    #pragma unroll
    for (int p = 0; p < 8; p++) { int idx = p * 64 + j; a[p] = __half22float2(buf[f][PADIDX(idx)]); }
    __syncthreads();   // all buf reads done; safe to reuse as fp16 transpose tile
    #pragma unroll
    for (int p = 1; p < 8; p++) a[p] = cmul(a[p], tw[p * j]);
    dft8(a, X);

    // stage result into fp16 transpose tile: tile[u*9 + f]
    __half2* tile = &buf[0][0];
    #pragma unroll
    for (int q = 0; q < 8; q++) {
        int u = q * 64 + j;
        tile[u * 9 + f] = __floats2half2_rn(X[q].x, X[q].y);
    }
    __syncthreads();

    // coalesced transposed fp16 write: 8 consecutive y per u = 32B sector
    int yo = tid & 7;          // y offset within block
    int ub = tid >> 3;         // 0..63
    __half2* dst = g_Bf + (size_t)b * NPIX + y0 + yo;
    #pragma unroll
    for (int i = 0; i < 8; i++) {
        int u = ub + i * 64;
        dst[(size_t)u * NS] = tile[u * 9 + yo];
    }
}

// -------- K2: column FFT on conjugate-partner row pairs + fused PSD --------
// 256 threads, 2 row-pairs (4 row FFTs) per block. grid (128, NB).
// NOTE: fft2's exchanges/res MUST stay fp32 — final-spectrum DC ~1.3e5 would
// overflow fp16. Twiddles from g_tw (fft2's MUFU is loaded by __log2f).
// g_Bf read with .cs (last use; L2-resident from pass 1).
// Half-domain PSD via PSD(-k)=PSD(k); mask box [-64,63] checked per side.
__global__ void __launch_bounds__(256) k_fft2_psd() {
    __shared__ float2 tw[512];
    __shared__ float2 buf2[4][576];   // 18432 B; reused as res[4][512] (16384 B)
    __shared__ float  wsum[8];

    int tid = threadIdx.x;
    tw[tid] = g_tw[tid];
    tw[tid + 256] = g_tw[tid + 256];

    int s    = tid >> 7;           // sub-block (pair) 0..1
    int tid2 = tid & 127;
    int f    = tid2 >> 6;          // 0 or 1 within pair
    int j    = tid2 & 63;
    int b    = blockIdx.y;
    int v    = blockIdx.x * 2 + s; // 0..255
    int rA = v;
    int rB = (v == 0) ? 256 : 512 - v;
    int r  = f ? rB : rA;
    float2* buf = &buf2[s * 2 + f][0];
    float2* res = &buf2[0][0];     // res[(s*2+h)*512 + e]

    const __half2* rp = g_Bf + (size_t)b * NPIX + (size_t)r * NS;

    float2 a[8], X[8];
    #pragma unroll
    for (int p = 0; p < 8; p++) a[p] = __half22float2(__ldcs(rp + p * 64 + j));

    dft8(a, X);
    #pragma unroll
    for (int q = 0; q < 8; q++) { int idx = j * 8 + q; buf[PADIDX(idx)] = X[q]; }
    __syncthreads();

    #pragma unroll
    for (int p = 0; p < 8; p++) { int idx = p * 64 + j; a[p] = buf[PADIDX(idx)]; }
    __syncthreads();
    int k1 = j & 7, b1 = j >> 3;
    #pragma unroll
    for (int p = 1; p < 8; p++) a[p] = cmul(a[p], tw[(p * k1) << 3]);
    dft8(a, X);
    #pragma unroll
    for (int q = 0; q < 8; q++) { int idx = b1 * 64 + q * 8 + k1; buf[PADIDX(idx)] = X[q]; }
    __syncthreads();

    #pragma unroll
    for (int p = 0; p < 8; p++) { int idx = p * 64 + j; a[p] = buf[PADIDX(idx)]; }
    __syncthreads();   // all buf reads done; safe to overwrite as res
    #pragma unroll
    for (int p = 1; p < 8; p++) a[p] = cmul(a[p], tw[p * j]);
    dft8(a, X);
    #pragma unroll
    for (int q = 0; q < 8; q++) res[(s * 2 + f) * 512 + q * 64 + j] = X[q];
    __syncthreads();

    bool lowA = (rA < 64) | (rA >= 448);
    bool lowB = (rB < 64) | (rB >= 448);

    float acc = 0.0f;
    if (v != 0) {
        // Half-domain: element (rA, e) with partner (rB, (512-e)&511).
        #pragma unroll
        for (int it = 0; it < 4; it++) {
            int e  = it * 128 + tid2;      // 0..511
            int e2 = (512 - e) & 511;
            bool m1 = !(lowA & ((e  < 64) | (e  >= 448)));   // mask(rA, e)
            bool m2 = !(lowB & ((e2 < 64) | (e2 >= 448)));   // mask(rB, -e)
            int wi = (int)m1 + (int)m2;
            if (wi == 0) continue;

            float2 z1 = res[(s * 2 + 0) * 512 + e];
            float2 z2 = res[(s * 2 + 1) * 512 + e2];

            float ra = 0.5f * (z1.x + z2.x), ia = 0.5f * (z1.y - z2.y);
            float rb = 0.5f * (z1.y + z2.y), ib = 0.5f * (z2.x - z1.x);
            float pa = fmaf(ra, ra, ia * ia) + 1e-10f;
            float pb = fmaf(rb, rb, ib * ib) + 1e-10f;
            acc += (float)wi * (__log2f(pa) - __log2f(pb));
        }
    } else {
        // Self-paired rows (u=0 and u=256): full domain, partner within same row.
        #pragma unroll
        for (int it = 0; it < 8; it++) {
            int i = it * 128 + tid2;       // 0..1023 over the pair's 2 rows
            int h = i >> 9;                // 0 -> row rA, 1 -> row rB
            int e = i & 511;
            bool lowr = h ? lowB : lowA;
            bool lowe = (e < 64) | (e >= 448);
            if (lowr & lowe) continue;

            float2 z1 = res[(s * 2 + h) * 512 + e];
            float2 z2 = res[(s * 2 + h) * 512 + ((512 - e) & 511)];

            float ra = 0.5f * (z1.x + z2.x), ia = 0.5f * (z1.y - z2.y);
            float rb = 0.5f * (z1.y + z2.y), ib = 0.5f * (z2.x - z1.x);
            float pa = fmaf(ra, ra, ia * ia) + 1e-10f;
            float pb = fmaf(rb, rb, ib * ib) + 1e-10f;
            acc += __log2f(pa) - __log2f(pb);
        }
    }

    // warp reduce (fixed order -> deterministic), then 4 warps per sub-block
    #pragma unroll
    for (int o = 16; o > 0; o >>= 1) acc += __shfl_down_sync(0xFFFFFFFFu, acc, o);
    if ((tid & 31) == 0) wsum[tid >> 5] = acc;
    __syncthreads();
    if (tid < 2) {
        int ss = tid;
        float d = wsum[ss * 4] + wsum[ss * 4 + 1] + wsum[ss * 4 + 2] + wsum[ss * 4 + 3];
        g_part[b][blockIdx.x * 2 + ss] = d;   // no atomics -> deterministic
    }
}

// -------- K3: finalize (parallel, coalesced, deterministic) --------
__global__ void __launch_bounds__(1024) k_final(float* __restrict__ out) {
    int t = threadIdx.x;
    int b = t >> 4, i = t & 15;
    float s = 0.0f;
    #pragma unroll
    for (int k = 0; k < 16; k++) s += g_part[b][i + k * 16];

    __shared__ float sh[64][17];
    __shared__ float red[64];
    sh[b][i] = s;
    __syncthreads();

    if (t < 64) {
        float d = 0.0f;
        #pragma unroll
        for (int k = 0; k < 16; k++) d += sh[t][k];
        red[t] = fabsf(d);
    }
    __syncthreads();
    #pragma unroll
    for (int s2 = 32; s2 > 0; s2 >>= 1) {
        if (t < s2) red[t] += red[t + s2];
        __syncthreads();
    }
    if (t == 0) out[0] = red[0] * (0.30102999566398119521f / (HF_COUNT * 64.0f));
}

// -------- launch --------
extern "C" void kernel_launch(void* const* d_in, const int* in_sizes, int n_in,
                              void* d_out, int out_size) {
    const float* gen = (const float*)d_in[0];
    const float* tgt = (const float*)d_in[1];
    float* out = (float*)d_out;
    (void)in_sizes; (void)n_in; (void)out_size;

    k_fft1<<<NB * 64, 512>>>(gen, tgt);        // fused gray + row FFT + transpose (+ twiddle publish)
    {
        dim3 g(128, NB);
        k_fft2_psd<<<g, 256>>>();              // column FFT + fused PSD (symmetry-halved)
    }
    k_final<<<1, 1024>>>(out);
}